// round 2
// baseline (speedup 1.0000x reference)
#include <cuda_runtime.h>
#include <math.h>
#include <stdint.h>

#define Bz 8
#define Nn 4096
#define Mm 2048
#define H2 128
#define KN 32
#define CAP 512

__device__ float g_A[Bz * Nn * 64];     // x @ W1[:64] + b1
__device__ int   g_idx[Bz * Mm];        // FPS indices
__device__ int   g_nbr[Bz * Mm * KN];   // in-radius neighbors, front-packed, -1 pad

__device__ __forceinline__ unsigned long long umax64(unsigned long long a, unsigned long long b){return a>b?a:b;}
__device__ __forceinline__ unsigned long long umin64(unsigned long long a, unsigned long long b){return a<b?a:b;}

// ---------------- K0: A = x @ W1[0:64,:] + b1 ----------------
__global__ void __launch_bounds__(256) k0_feat(const float* __restrict__ x,
                                               const float* __restrict__ W1,
                                               const float* __restrict__ b1) {
    __shared__ float xs[4 * 64];
    int t = threadIdx.x;
    int c = t & 63, rs = t >> 6;
    float w[64];
#pragma unroll
    for (int f = 0; f < 64; f++) w[f] = W1[f * 64 + c];
    float bb = b1[c];
    int base = blockIdx.x * 128;
    const float4* xs4 = (const float4*)xs;
    for (int r0 = 0; r0 < 128; r0 += 4) {
        int row = base + r0 + rs;
        __syncthreads();
        xs[rs * 64 + c] = x[(size_t)row * 64 + c];
        __syncthreads();
        float a0 = bb, a1 = 0.f, a2 = 0.f, a3 = 0.f;
#pragma unroll
        for (int q = 0; q < 16; q++) {
            float4 xv = xs4[rs * 16 + q];
            a0 = fmaf(xv.x, w[4*q+0], a0);
            a1 = fmaf(xv.y, w[4*q+1], a1);
            a2 = fmaf(xv.z, w[4*q+2], a2);
            a3 = fmaf(xv.w, w[4*q+3], a3);
        }
        g_A[(size_t)row * 64 + c] = (a0 + a1) + (a2 + a3);
    }
}

// ---------------- K1: FPS, 1 block per batch, bit-exact non-FMA ----------------
__global__ void __launch_bounds__(512) k1_fps(const float* __restrict__ pos) {
    extern __shared__ float sm1[];
    float* spx = sm1;
    float* spy = sm1 + Nn;
    float* spz = sm1 + 2 * Nn;
    unsigned long long* swk = (unsigned long long*)(sm1 + 3 * Nn);
    unsigned* swin = (unsigned*)(swk + 16);

    int b = blockIdx.x, t = threadIdx.x;
    const float* p = pos + (size_t)b * Nn * 3;
    float px[8], py[8], pz[8], md[8];
#pragma unroll
    for (int r = 0; r < 8; r++) {
        int pi = r * 512 + t;
        float a = p[pi*3], bb = p[pi*3+1], cc = p[pi*3+2];
        px[r] = a; py[r] = bb; pz[r] = cc;
        spx[pi] = a; spy[pi] = bb; spz[pi] = cc;
        md[r] = __int_as_float(0x7f800000);
    }
    if (t == 0) g_idx[b * Mm] = 0;
    __syncthreads();
    float lx = spx[0], ly = spy[0], lz = spz[0];

    for (int m = 1; m < Mm; m++) {
        float bv = -1.f; int bi = 0;
#pragma unroll
        for (int r = 0; r < 8; r++) {
            float dx = __fsub_rn(px[r], lx);
            float dy = __fsub_rn(py[r], ly);
            float dz = __fsub_rn(pz[r], lz);
            float d = __fadd_rn(__fadd_rn(__fmul_rn(dx,dx), __fmul_rn(dy,dy)), __fmul_rn(dz,dz));
            float v = fminf(md[r], d);
            md[r] = v;
            if (v > bv) { bv = v; bi = r * 512 + t; }
        }
        unsigned long long key = ((unsigned long long)__float_as_uint(bv) << 32) | (unsigned)(~bi);
#pragma unroll
        for (int o = 16; o > 0; o >>= 1) key = umax64(key, __shfl_down_sync(0xffffffffu, key, o));
        if ((t & 31) == 0) swk[t >> 5] = key;
        __syncthreads();
        if (t < 32) {
            unsigned long long k2 = (t < 16) ? swk[t] : 0ull;
#pragma unroll
            for (int o = 8; o > 0; o >>= 1) k2 = umax64(k2, __shfl_down_sync(0xffffffffu, k2, o));
            if (t == 0) {
                unsigned wi = ~(unsigned)k2;
                *swin = wi;
                g_idx[b * Mm + m] = (int)wi;
            }
        }
        __syncthreads();
        unsigned wi = *swin;
        lx = spx[wi]; ly = spy[wi]; lz = spz[wi];
    }
}

// ---------------- K2: radius compaction + exact 32-smallest; also pos_s/norm_s ----------------
__global__ void __launch_bounds__(256) k2_nbr(const float* __restrict__ pos,
                                              const float* __restrict__ norm,
                                              float* __restrict__ out_pos,
                                              float* __restrict__ out_norm) {
    extern __shared__ float sm2[];
    float* spx = sm2;
    float* spy = sm2 + Nn;
    float* spz = sm2 + 2 * Nn;
    float* sps = sm2 + 3 * Nn;
    float* cdist = sm2 + 4 * Nn;                 // [8][CAP]
    int* cidx = (int*)(cdist + 8 * CAP);         // [8][CAP]

    int b = blockIdx.y, t = threadIdx.x;
    const float* p = pos + (size_t)b * Nn * 3;
    for (int i = t; i < Nn; i += 256) {
        float a = p[i*3], bb = p[i*3+1], cc = p[i*3+2];
        spx[i] = a; spy[i] = bb; spz[i] = cc;
        sps[i] = __fadd_rn(__fadd_rn(__fmul_rn(a,a), __fmul_rn(bb,bb)), __fmul_rn(cc,cc));
    }
    __syncthreads();

    int w = t >> 5, lane = t & 31;
    int m = blockIdx.x * 8 + w;
    int ci = g_idx[b * Mm + m];
    float cx = spx[ci], cy = spy[ci], cz = spz[ci], cs = sps[ci];
    if (lane == 0) {
        size_t o = ((size_t)b * Mm + m) * 3;
        out_pos[o] = cx; out_pos[o+1] = cy; out_pos[o+2] = cz;
        size_t gi = ((size_t)b * Nn + ci) * 3;
        out_norm[o] = norm[gi]; out_norm[o+1] = norm[gi+1]; out_norm[o+2] = norm[gi+2];
    }
    float* myd = cdist + w * CAP;
    int* myi = cidx + w * CAP;
    int cnt = 0;
    for (int n0 = lane; n0 < Nn; n0 += 32) {
        float dot = __fadd_rn(__fadd_rn(__fmul_rn(cx,spx[n0]), __fmul_rn(cy,spy[n0])), __fmul_rn(cz,spz[n0]));
        float d2 = __fsub_rn(__fadd_rn(cs, sps[n0]), __fmul_rn(2.0f, dot));
        bool pr = (d2 <= 0.04f);
        unsigned msk = __ballot_sync(0xffffffffu, pr);
        if (pr) {
            int ps_ = cnt + __popc(msk & ((1u << lane) - 1u));
            if (ps_ < CAP) { myd[ps_] = d2; myi[ps_] = n0; }
        }
        cnt += __popc(msk);
    }
    if (cnt > CAP) cnt = CAP;
    int outn = cnt < KN ? cnt : KN;
    size_t nb = ((size_t)b * Mm + m) * KN;
    for (int r = 0; r < outn; r++) {
        unsigned long long best = 0xFFFFFFFFFFFFFFFFull;
        for (int i = lane; i < cnt; i += 32) {
            unsigned u = __float_as_uint(myd[i]);
            u ^= ((unsigned)(((int)u) >> 31)) | 0x80000000u;
            best = umin64(best, ((unsigned long long)u << 32) | (unsigned)i);
        }
#pragma unroll
        for (int o = 16; o > 0; o >>= 1) best = umin64(best, __shfl_down_sync(0xffffffffu, best, o));
        best = __shfl_sync(0xffffffffu, best, 0);
        int slot = (int)(unsigned)best;
        if (lane == 0) {
            g_nbr[nb + r] = myi[slot];
            myd[slot] = __int_as_float(0x7f800000);
        }
        __syncwarp();
    }
    for (int r2 = outn + lane; r2 < KN; r2 += 32) g_nbr[nb + r2] = -1;
}

// ---------------- K3: fused PPF + MLP + max ----------------
__device__ __forceinline__ float get_angle(float ax, float ay, float az,
                                           float bx, float by, float bz) {
    float cx = ay*bz - az*by;
    float cy = az*bx - ax*bz;
    float cz = ax*by - ay*bx;
    float cn2 = cx*cx + cy*cy + cz*cz;
    float cn = cn2 > 0.f ? sqrtf(cn2) : 0.f;
    float d = ax*bx + ay*by + az*bz;
    if (cn == 0.f && d == 0.f) d = 1.f;
    return atan2f(cn, d);
}

__global__ void __launch_bounds__(256) k3_mlp(const float* __restrict__ pos,
                                              const float* __restrict__ norm,
                                              const float* __restrict__ W1,
                                              const float* __restrict__ W2,
                                              const float* __restrict__ b2,
                                              const float* __restrict__ out_pos,
                                              const float* __restrict__ out_norm,
                                              float* __restrict__ out) {
    extern __shared__ char sm3[];
    float4* sh1 = (float4*)sm3;                   // [256][16] float4, XOR-swizzled
    int* snbr = (int*)(sm3 + 256 * 64 * 4);       // 256
    float* sW1p = (float*)(snbr + 256);           // W1 rows 64..67 (4x64)
    float* scp = sW1p + 256;                      // 8x3
    float* scn = scp + 24;                        // 8x3

    int t = threadIdx.x, b = blockIdx.y;
    int cb = blockIdx.x * 8;
    snbr[t] = g_nbr[((size_t)b * Mm + cb) * KN + t];
    sW1p[t] = W1[64 * 64 + t];
    if (t < 24) {
        size_t o = ((size_t)b * Mm + cb) * 3 + t;
        scp[t] = out_pos[o];
        scn[t] = out_norm[o];
    }
    __syncthreads();

    { // phase A/B: thread = (center g, neighbor k) -> h1 row into smem
        int g = t >> 5;
        int j = snbr[t];
        if (j >= 0) {
            float cx = scp[g*3], cy = scp[g*3+1], cz = scp[g*3+2];
            float nix = scn[g*3], niy = scn[g*3+1], niz = scn[g*3+2];
            size_t pj = ((size_t)b * Nn + j) * 3;
            float dx = pos[pj] - cx, dy = pos[pj+1] - cy, dz = pos[pj+2] - cz;
            float njx = norm[pj], njy = norm[pj+1], njz = norm[pj+2];
            float dd = dx*dx + dy*dy + dz*dz;
            float f0 = dd > 0.f ? sqrtf(dd) : 0.f;
            float f1 = get_angle(nix, niy, niz, dx, dy, dz);
            float f2 = get_angle(njx, njy, njz, dx, dy, dz);
            float f3 = get_angle(nix, niy, niz, njx, njy, njz);
            const float4* Ar = (const float4*)(g_A + ((size_t)b * Nn + j) * 64);
            const float4* w1p = (const float4*)sW1p;
            int sw = t & 15;
#pragma unroll
            for (int q = 0; q < 16; q++) {
                float4 a = Ar[q];
                float4 w0 = w1p[q], w1v = w1p[16+q], w2v = w1p[32+q], w3v = w1p[48+q];
                a.x = fmaxf(fmaf(f3,w3v.x, fmaf(f2,w2v.x, fmaf(f1,w1v.x, fmaf(f0,w0.x, a.x)))), 0.f);
                a.y = fmaxf(fmaf(f3,w3v.y, fmaf(f2,w2v.y, fmaf(f1,w1v.y, fmaf(f0,w0.y, a.y)))), 0.f);
                a.z = fmaxf(fmaf(f3,w3v.z, fmaf(f2,w2v.z, fmaf(f1,w1v.z, fmaf(f0,w0.z, a.z)))), 0.f);
                a.w = fmaxf(fmaf(f3,w3v.w, fmaf(f2,w2v.w, fmaf(f1,w1v.w, fmaf(f0,w0.w, a.w)))), 0.f);
                sh1[t * 16 + (q ^ sw)] = a;
            }
        }
    }
    __syncthreads();

    { // phase C: thread = (g-half, out channel); broadcast smem reads
        int c = t & 127, gh = t >> 7;
        float w2r[64];
#pragma unroll
        for (int i = 0; i < 64; i++) w2r[i] = W2[i * 128 + c];
        float bb2 = b2[c];
#pragma unroll
        for (int g0 = 0; g0 < 8; g0 += 2) {
            int gg = g0 + gh;
            float mx = __int_as_float(0xff800000);
            for (int k = 0; k < KN; k++) {
                int jj = snbr[gg * 32 + k];
                if (jj < 0) break;                  // warp-uniform
                int pp = gg * 32 + k, sw = pp & 15;
                float z0 = bb2, z1 = 0.f, z2 = 0.f, z3 = 0.f;
#pragma unroll
                for (int q = 0; q < 16; q++) {
                    float4 h = sh1[pp * 16 + (q ^ sw)];
                    z0 = fmaf(h.x, w2r[4*q+0], z0);
                    z1 = fmaf(h.y, w2r[4*q+1], z1);
                    z2 = fmaf(h.z, w2r[4*q+2], z2);
                    z3 = fmaf(h.w, w2r[4*q+3], z3);
                }
                mx = fmaxf(mx, (z0 + z1) + (z2 + z3));
            }
            out[((size_t)(b * Mm + cb + gg)) * 128 + c] = fmaxf(mx, 0.f);
        }
    }
}

extern "C" void kernel_launch(void* const* d_in, const int* in_sizes, int n_in,
                              void* d_out, int out_size) {
    const float* x    = (const float*)d_in[0];
    const float* pos  = (const float*)d_in[1];
    const float* norm = (const float*)d_in[2];
    const float* W1   = (const float*)d_in[3];
    const float* b1   = (const float*)d_in[4];
    const float* W2   = (const float*)d_in[5];
    const float* b2   = (const float*)d_in[6];

    float* out      = (float*)d_out;
    float* out_pos  = out + (size_t)Bz * Mm * H2;
    float* out_norm = out_pos + (size_t)Bz * Mm * 3;

    const int smem1 = 3 * Nn * 4 + 16 * 8 + 16;
    const int smem2 = 4 * Nn * 4 + 8 * CAP * 8;
    const int smem3 = 256 * 64 * 4 + 256 * 4 + 256 * 4 + 48 * 4;

    cudaFuncSetAttribute(k1_fps, cudaFuncAttributeMaxDynamicSharedMemorySize, smem1);
    cudaFuncSetAttribute(k2_nbr, cudaFuncAttributeMaxDynamicSharedMemorySize, smem2);
    cudaFuncSetAttribute(k3_mlp, cudaFuncAttributeMaxDynamicSharedMemorySize, smem3);

    k0_feat<<<(Bz * Nn) / 128, 256>>>(x, W1, b1);
    k1_fps<<<Bz, 512, smem1>>>(pos);
    k2_nbr<<<dim3(Mm / 8, Bz), 256, smem2>>>(pos, norm, out_pos, out_norm);
    k3_mlp<<<dim3(Mm / 8, Bz), 256, smem3>>>(pos, norm, W1, W2, b2, out_pos, out_norm, out);
}

// round 3
// speedup vs baseline: 1.1868x; 1.1868x over previous
#include <cuda_runtime.h>
#include <math.h>
#include <stdint.h>

#define Bz 8
#define Nn 4096
#define Mm 2048
#define H2 128
#define KN 32
#define CAP 512

__device__ float g_A[Bz * Nn * 64];     // x @ W1[:64] + b1
__device__ int   g_idx[Bz * Mm];        // FPS indices
__device__ int   g_nbr[Bz * Mm * KN];   // in-radius neighbors, front-packed, -1 pad

__device__ __forceinline__ unsigned long long umax64(unsigned long long a, unsigned long long b){return a>b?a:b;}
__device__ __forceinline__ unsigned long long umin64(unsigned long long a, unsigned long long b){return a<b?a:b;}

// packed f32x2 helpers (rn rounding identical to scalar)
__device__ __forceinline__ unsigned long long pk2(float lo, float hi){
    unsigned long long r; asm("mov.b64 %0, {%1, %2};" : "=l"(r) : "f"(lo), "f"(hi)); return r;
}
__device__ __forceinline__ void upk2(unsigned long long v, float& lo, float& hi){
    asm("mov.b64 {%0, %1}, %2;" : "=f"(lo), "=f"(hi) : "l"(v));
}
__device__ __forceinline__ unsigned long long addx2(unsigned long long a, unsigned long long b){
    unsigned long long r; asm("add.rn.f32x2 %0, %1, %2;" : "=l"(r) : "l"(a), "l"(b)); return r;
}
__device__ __forceinline__ unsigned long long mulx2(unsigned long long a, unsigned long long b){
    unsigned long long r; asm("mul.rn.f32x2 %0, %1, %2;" : "=l"(r) : "l"(a), "l"(b)); return r;
}

// ---------------- K0: A = x @ W1[0:64,:] + b1 ----------------
__global__ void __launch_bounds__(256) k0_feat(const float* __restrict__ x,
                                               const float* __restrict__ W1,
                                               const float* __restrict__ b1) {
    __shared__ float xs[4 * 64];
    int t = threadIdx.x;
    int c = t & 63, rs = t >> 6;
    float w[64];
#pragma unroll
    for (int f = 0; f < 64; f++) w[f] = W1[f * 64 + c];
    float bb = b1[c];
    int base = blockIdx.x * 128;
    const float4* xs4 = (const float4*)xs;
    for (int r0 = 0; r0 < 128; r0 += 4) {
        int row = base + r0 + rs;
        __syncthreads();
        xs[rs * 64 + c] = x[(size_t)row * 64 + c];
        __syncthreads();
        float a0 = bb, a1 = 0.f, a2 = 0.f, a3 = 0.f;
#pragma unroll
        for (int q = 0; q < 16; q++) {
            float4 xv = xs4[rs * 16 + q];
            a0 = fmaf(xv.x, w[4*q+0], a0);
            a1 = fmaf(xv.y, w[4*q+1], a1);
            a2 = fmaf(xv.z, w[4*q+2], a2);
            a3 = fmaf(xv.w, w[4*q+3], a3);
        }
        g_A[(size_t)row * 64 + c] = (a0 + a1) + (a2 + a3);
    }
}

// ---------------- K1: FPS, 1 block/batch, f32x2 packed, 1 barrier/iter ----------------
// Arithmetic is bit-identical to round-2 passing version:
//   d = ((dx*dx + dy*dy) + dz*dz), dx = px + (-lx)  (rn, no FMA contraction)
__global__ void __launch_bounds__(256) k1_fps(const float* __restrict__ pos) {
    extern __shared__ float sm1[];
    float* spx = sm1;
    float* spy = sm1 + Nn;
    float* spz = sm1 + 2 * Nn;
    unsigned long long* swk = (unsigned long long*)(sm1 + 3 * Nn);  // [2][8]

    int b = blockIdx.x, t = threadIdx.x;
    const float* p = pos + (size_t)b * Nn * 3;
    for (int i = t; i < Nn; i += 256) {
        spx[i] = p[i*3]; spy[i] = p[i*3+1]; spz[i] = p[i*3+2];
    }
    if (t == 0) g_idx[b * Mm] = 0;
    __syncthreads();

    // pack 16 points per thread as 8 f32x2 pairs
    unsigned long long PX[8], PY[8], PZ[8];
    float md[16];
    int base = t * 16;
#pragma unroll
    for (int q = 0; q < 8; q++) {
        PX[q] = pk2(spx[base + 2*q], spx[base + 2*q + 1]);
        PY[q] = pk2(spy[base + 2*q], spy[base + 2*q + 1]);
        PZ[q] = pk2(spz[base + 2*q], spz[base + 2*q + 1]);
        md[2*q] = __int_as_float(0x7f800000);
        md[2*q+1] = __int_as_float(0x7f800000);
    }
    float lx = spx[0], ly = spy[0], lz = spz[0];
    int w = t >> 5, lane = t & 31;
    unsigned par = 0;

    for (int m = 1; m < Mm; m++) {
        unsigned long long nlx = pk2(-lx, -lx);
        unsigned long long nly = pk2(-ly, -ly);
        unsigned long long nlz = pk2(-lz, -lz);
        float bv = -1.f; int bi = 0;
#pragma unroll
        for (int q = 0; q < 8; q++) {
            unsigned long long dx = addx2(PX[q], nlx);
            unsigned long long dy = addx2(PY[q], nly);
            unsigned long long dz = addx2(PZ[q], nlz);
            unsigned long long s = addx2(addx2(mulx2(dx,dx), mulx2(dy,dy)), mulx2(dz,dz));
            float d0, d1; upk2(s, d0, d1);
            float v0 = fminf(md[2*q], d0);   md[2*q]   = v0;
            float v1 = fminf(md[2*q+1], d1); md[2*q+1] = v1;
            if (v0 > bv) { bv = v0; bi = base + 2*q; }
            if (v1 > bv) { bv = v1; bi = base + 2*q + 1; }
        }
        unsigned long long key = ((unsigned long long)__float_as_uint(bv) << 32) | (unsigned)(~bi);
#pragma unroll
        for (int o = 16; o > 0; o >>= 1) key = umax64(key, __shfl_xor_sync(0xffffffffu, key, o));
        if (lane == 0) swk[par * 8 + w] = key;
        __syncthreads();
        const ulonglong2* kp = (const ulonglong2*)(swk + par * 8);
        ulonglong2 v0 = kp[0], v1 = kp[1], v2 = kp[2], v3 = kp[3];
        unsigned long long best = umax64(umax64(umax64(v0.x, v0.y), umax64(v1.x, v1.y)),
                                         umax64(umax64(v2.x, v2.y), umax64(v3.x, v3.y)));
        unsigned wi = ~(unsigned)best;
        if (t == 0) g_idx[b * Mm + m] = (int)wi;
        lx = spx[wi]; ly = spy[wi]; lz = spz[wi];
        par ^= 1;
    }
}

// ---------------- K2: radius compaction + exact 32-smallest; also pos_s/norm_s ----------------
__global__ void __launch_bounds__(256) k2_nbr(const float* __restrict__ pos,
                                              const float* __restrict__ norm,
                                              float* __restrict__ out_pos,
                                              float* __restrict__ out_norm) {
    extern __shared__ float sm2[];
    float* spx = sm2;
    float* spy = sm2 + Nn;
    float* spz = sm2 + 2 * Nn;
    float* sps = sm2 + 3 * Nn;
    float* cdist = sm2 + 4 * Nn;                 // [8][CAP]
    int* cidx = (int*)(cdist + 8 * CAP);         // [8][CAP]

    int b = blockIdx.y, t = threadIdx.x;
    const float* p = pos + (size_t)b * Nn * 3;
    for (int i = t; i < Nn; i += 256) {
        float a = p[i*3], bb = p[i*3+1], cc = p[i*3+2];
        spx[i] = a; spy[i] = bb; spz[i] = cc;
        sps[i] = __fadd_rn(__fadd_rn(__fmul_rn(a,a), __fmul_rn(bb,bb)), __fmul_rn(cc,cc));
    }
    __syncthreads();

    int w = t >> 5, lane = t & 31;
    int m = blockIdx.x * 8 + w;
    int ci = g_idx[b * Mm + m];
    float cx = spx[ci], cy = spy[ci], cz = spz[ci], cs = sps[ci];
    if (lane == 0) {
        size_t o = ((size_t)b * Mm + m) * 3;
        out_pos[o] = cx; out_pos[o+1] = cy; out_pos[o+2] = cz;
        size_t gi = ((size_t)b * Nn + ci) * 3;
        out_norm[o] = norm[gi]; out_norm[o+1] = norm[gi+1]; out_norm[o+2] = norm[gi+2];
    }
    float* myd = cdist + w * CAP;
    int* myi = cidx + w * CAP;
    int cnt = 0;
    for (int n0 = lane; n0 < Nn; n0 += 32) {
        float dot = __fadd_rn(__fadd_rn(__fmul_rn(cx,spx[n0]), __fmul_rn(cy,spy[n0])), __fmul_rn(cz,spz[n0]));
        float d2 = __fsub_rn(__fadd_rn(cs, sps[n0]), __fmul_rn(2.0f, dot));
        bool pr = (d2 <= 0.04f);
        unsigned msk = __ballot_sync(0xffffffffu, pr);
        if (pr) {
            int ps_ = cnt + __popc(msk & ((1u << lane) - 1u));
            if (ps_ < CAP) { myd[ps_] = d2; myi[ps_] = n0; }
        }
        cnt += __popc(msk);
    }
    if (cnt > CAP) cnt = CAP;
    int outn = cnt < KN ? cnt : KN;
    size_t nb = ((size_t)b * Mm + m) * KN;
    for (int r = 0; r < outn; r++) {
        unsigned long long best = 0xFFFFFFFFFFFFFFFFull;
        for (int i = lane; i < cnt; i += 32) {
            unsigned u = __float_as_uint(myd[i]);
            u ^= ((unsigned)(((int)u) >> 31)) | 0x80000000u;
            best = umin64(best, ((unsigned long long)u << 32) | (unsigned)i);
        }
#pragma unroll
        for (int o = 16; o > 0; o >>= 1) best = umin64(best, __shfl_down_sync(0xffffffffu, best, o));
        best = __shfl_sync(0xffffffffu, best, 0);
        int slot = (int)(unsigned)best;
        if (lane == 0) {
            g_nbr[nb + r] = myi[slot];
            myd[slot] = __int_as_float(0x7f800000);
        }
        __syncwarp();
    }
    for (int r2 = outn + lane; r2 < KN; r2 += 32) g_nbr[nb + r2] = -1;
}

// ---------------- K3: fused PPF + MLP + max (transposed h1 layout) ----------------
__device__ __forceinline__ float get_angle(float ax, float ay, float az,
                                           float bx, float by, float bz) {
    float cx = ay*bz - az*by;
    float cy = az*bx - ax*bz;
    float cz = ax*by - ay*bx;
    float cn2 = cx*cx + cy*cy + cz*cz;
    float cn = cn2 > 0.f ? sqrtf(cn2) : 0.f;
    float d = ax*bx + ay*by + az*bz;
    if (cn == 0.f && d == 0.f) d = 1.f;
    return atan2f(cn, d);
}

__global__ void __launch_bounds__(256) k3_mlp(const float* __restrict__ pos,
                                              const float* __restrict__ norm,
                                              const float* __restrict__ W1,
                                              const float* __restrict__ W2,
                                              const float* __restrict__ b2,
                                              const float* __restrict__ out_pos,
                                              const float* __restrict__ out_norm,
                                              float* __restrict__ out) {
    extern __shared__ char sm3[];
    float4* shT = (float4*)sm3;                   // [16][256] float4: h1T[q][pp]
    int* snbr = (int*)(sm3 + 16 * 256 * 16);      // 256
    int* scnt = snbr + 256;                       // 8
    float* sW1p = (float*)(scnt + 8);             // 4x64 (W1 rows 64..67)
    float* scp = sW1p + 256;                      // 8x3
    float* scn = scp + 24;                        // 8x3

    int t = threadIdx.x, b = blockIdx.y;
    int cb = blockIdx.x * 8;
    snbr[t] = g_nbr[((size_t)b * Mm + cb) * KN + t];
    sW1p[t] = W1[64 * 64 + t];
    if (t < 24) {
        size_t o = ((size_t)b * Mm + cb) * 3 + t;
        scp[t] = out_pos[o];
        scn[t] = out_norm[o];
    }
    __syncthreads();

    { // phase A: thread = (center g, neighbor k) -> h1 row into transposed smem
        int g = t >> 5, lane = t & 31;
        int j = snbr[t];
        unsigned msk = __ballot_sync(0xffffffffu, j >= 0);
        if (lane == 0) scnt[g] = __popc(msk);   // front-packed
        if (j >= 0) {
            float cx = scp[g*3], cy = scp[g*3+1], cz = scp[g*3+2];
            float nix = scn[g*3], niy = scn[g*3+1], niz = scn[g*3+2];
            size_t pj = ((size_t)b * Nn + j) * 3;
            float dx = pos[pj] - cx, dy = pos[pj+1] - cy, dz = pos[pj+2] - cz;
            float njx = norm[pj], njy = norm[pj+1], njz = norm[pj+2];
            float dd = dx*dx + dy*dy + dz*dz;
            float f0 = dd > 0.f ? sqrtf(dd) : 0.f;
            float f1 = get_angle(nix, niy, niz, dx, dy, dz);
            float f2 = get_angle(njx, njy, njz, dx, dy, dz);
            float f3 = get_angle(nix, niy, niz, njx, njy, njz);
            const float4* Ar = (const float4*)(g_A + ((size_t)b * Nn + j) * 64);
            const float4* w1p = (const float4*)sW1p;
#pragma unroll
            for (int q = 0; q < 16; q++) {
                float4 a = Ar[q];
                float4 w0 = w1p[q], w1v = w1p[16+q], w2v = w1p[32+q], w3v = w1p[48+q];
                a.x = fmaxf(fmaf(f3,w3v.x, fmaf(f2,w2v.x, fmaf(f1,w1v.x, fmaf(f0,w0.x, a.x)))), 0.f);
                a.y = fmaxf(fmaf(f3,w3v.y, fmaf(f2,w2v.y, fmaf(f1,w1v.y, fmaf(f0,w0.y, a.y)))), 0.f);
                a.z = fmaxf(fmaf(f3,w3v.z, fmaf(f2,w2v.z, fmaf(f1,w1v.z, fmaf(f0,w0.z, a.z)))), 0.f);
                a.w = fmaxf(fmaf(f3,w3v.w, fmaf(f2,w2v.w, fmaf(f1,w1v.w, fmaf(f0,w0.w, a.w)))), 0.f);
                shT[q * 256 + t] = a;   // consecutive t -> conflict-free STS.128
            }
        }
    }
    __syncthreads();

    { // phase C: thread = (g-half, out channel); broadcast reads, immediate offsets
        int c = t & 127, gh = t >> 7;
        float w2r[64];
#pragma unroll
        for (int i = 0; i < 64; i++) w2r[i] = W2[i * 128 + c];
        float bb2 = b2[c];
#pragma unroll
        for (int g0 = 0; g0 < 8; g0 += 2) {
            int gg = g0 + gh;
            int kn = scnt[gg];                    // warp-uniform
            float mx = __int_as_float(0xff800000);
            const float4* hrow = shT + gg * 32;
            for (int k = 0; k < kn; k++) {
                float z0 = bb2, z1 = 0.f, z2 = 0.f, z3 = 0.f;
#pragma unroll
                for (int q = 0; q < 16; q++) {
                    float4 h = hrow[q * 256 + k];
                    z0 = fmaf(h.x, w2r[4*q+0], z0);
                    z1 = fmaf(h.y, w2r[4*q+1], z1);
                    z2 = fmaf(h.z, w2r[4*q+2], z2);
                    z3 = fmaf(h.w, w2r[4*q+3], z3);
                }
                mx = fmaxf(mx, (z0 + z1) + (z2 + z3));
            }
            out[((size_t)(b * Mm + cb + gg)) * 128 + c] = fmaxf(mx, 0.f);
        }
    }
}

extern "C" void kernel_launch(void* const* d_in, const int* in_sizes, int n_in,
                              void* d_out, int out_size) {
    const float* x    = (const float*)d_in[0];
    const float* pos  = (const float*)d_in[1];
    const float* norm = (const float*)d_in[2];
    const float* W1   = (const float*)d_in[3];
    const float* b1   = (const float*)d_in[4];
    const float* W2   = (const float*)d_in[5];
    const float* b2   = (const float*)d_in[6];

    float* out      = (float*)d_out;
    float* out_pos  = out + (size_t)Bz * Mm * H2;
    float* out_norm = out_pos + (size_t)Bz * Mm * 3;

    const int smem1 = 3 * Nn * 4 + 2 * 8 * 8;
    const int smem2 = 4 * Nn * 4 + 8 * CAP * 8;
    const int smem3 = 16 * 256 * 16 + 256 * 4 + 8 * 4 + 256 * 4 + 48 * 4;

    cudaFuncSetAttribute(k1_fps, cudaFuncAttributeMaxDynamicSharedMemorySize, smem1);
    cudaFuncSetAttribute(k2_nbr, cudaFuncAttributeMaxDynamicSharedMemorySize, smem2);
    cudaFuncSetAttribute(k3_mlp, cudaFuncAttributeMaxDynamicSharedMemorySize, smem3);

    k0_feat<<<(Bz * Nn) / 128, 256>>>(x, W1, b1);
    k1_fps<<<Bz, 256, smem1>>>(pos);
    k2_nbr<<<dim3(Mm / 8, Bz), 256, smem2>>>(pos, norm, out_pos, out_norm);
    k3_mlp<<<dim3(Mm / 8, Bz), 256, smem3>>>(pos, norm, W1, W2, b2, out_pos, out_norm, out);
}